// round 16
// baseline (speedup 1.0000x reference)
#include <cuda_runtime.h>

#define FEATURES 512
#define NB 64
#define NKNOTS 68
#define BATCH 2048
#define NROW 65   // 64 splines + sentinel row

// Per (feature, spline) row, 2 x float4:
//   ra = (c0, c1, c2, c3)
//   rb = (c4, w, k_break = k[i], k_new = k[i+4])
// Sentinel row i=64: ra = (k0,k1,k2,k3) [prologue knots], rb = (0,0,2.0,0).
__device__ float4 g_rows[FEATURES * NROW * 2];
// Per-feature value-sorted batch: x values and original b indices.
__device__ float g_xs[FEATURES * BATCH];
__device__ int   g_pb[FEATURES * BATCH];

// Merged setup kernel: blocks [0,512) do the per-feature bucket sort,
// blocks [512, 512+130) build the coef/knot rows.
__global__ void __launch_bounds__(256)
setup_kernel(const float* __restrict__ X,
             const float* __restrict__ knots,
             const float* __restrict__ weights) {
    const int t = threadIdx.x;

    if (blockIdx.x < FEATURES) {
        // ---- per-feature counting sort by bucket = floor(64x) ----
        // Any batch permutation is bit-neutral (each out depends only on its x).
        __shared__ int hist[64];
        __shared__ int offs[64];
        const int f = blockIdx.x;

        if (t < 64) hist[t] = 0;
        __syncthreads();

        float xv[8];
        int   bk[8];
#pragma unroll
        for (int r = 0; r < 8; r++) {
            int b = r * 256 + t;
            float x = X[b * FEATURES + f];
            int k = (int)(x * 64.0f);
            k = min(max(k, 0), 63);
            xv[r] = x; bk[r] = k;
            atomicAdd(&hist[k], 1);
        }
        __syncthreads();

        if (t == 0) {
            int s = 0;
#pragma unroll
            for (int i = 0; i < 64; i++) { offs[i] = s; s += hist[i]; }
        }
        __syncthreads();

#pragma unroll
        for (int r = 0; r < 8; r++) {
            int pos = atomicAdd(&offs[bk[r]], 1);
            g_xs[f * BATCH + pos] = xv[r];
            g_pb[f * BATCH + pos] = r * 256 + t;
        }
    } else {
        // ---- row prep ----
        int idx = (blockIdx.x - FEATURES) * 256 + t;   // f*NROW + i
        if (idx >= FEATURES * NROW) return;
        int f = idx / NROW, i = idx % NROW;
        const float* kr = knots + f * NKNOTS;
        float4 ra, rb;
        if (i < NB) {
            float kw[5];
#pragma unroll
            for (int j = 0; j < 5; j++) kw[j] = kr[i + j];
            float c[5];
#pragma unroll
            for (int j = 0; j < 5; j++) {
                float p = 1.0f;                       // P1: sequential left fold
#pragma unroll
                for (int jp = 0; jp < 5; jp++) {
                    float d = (jp == j) ? 1.0f : __fsub_rn(kw[jp], kw[j]);
                    p = __fmul_rn(p, d);
                }
                c[j] = __fdiv_rn(1.0f, p);
            }
            ra = make_float4(c[0], c[1], c[2], c[3]);
            rb = make_float4(c[4], weights[f * NB + i], kr[i], kr[i + 4]);
        } else {
            ra = make_float4(kr[0], kr[1], kr[2], kr[3]);
            rb = make_float4(0.0f, 0.0f, 2.0f, 0.0f);
        }
        g_rows[idx * 2 + 0] = ra;
        g_rows[idx * 2 + 1] = rb;
    }
}

// cube with the exact rounding chain of the reference: (r*r)*r
__device__ __forceinline__ float cube_relu(float x, float k) {
    float r = fmaxf(__fsub_rn(x, k), 0.0f);
    return __fmul_rn(__fmul_rn(r, r), r);
}

__global__ void __launch_bounds__(256)
bspline_kernel(float* __restrict__ out) {
    __shared__ __align__(16) float4 sr[NROW * 2];
    __shared__ float skb[NB];

    const int f = blockIdx.y;
    const int t = threadIdx.x;
    if (t < NROW * 2) sr[t] = g_rows[f * NROW * 2 + t];
    __syncthreads();
    if (t < NB) skb[t] = sr[t * 2 + 1].z;   // break knots k[0..63]
    __syncthreads();

    const int slot = blockIdx.x * 256 + t;
    const float x = g_xs[f * BATCH + slot];     // coalesced, value-sorted
    const int   bo = g_pb[f * BATCH + slot];

    // Trip count n = #{ i < 64 : k_i < x } via branchless binary search
    // (exact same float predicate as the old per-iteration break).
    int n = 0;
#pragma unroll
    for (int s = 32; s >= 1; s >>= 1)
        if (skb[n + s - 1] < x) n += s;          // lower_bound over 63 elems
    if (n == 63 && skb[63] < x) n = 64;          // handle the last element

    // Prologue: r3 slots for knots k[0..3] (stored in sentinel row's ra).
    const float4 hk = sr[64 * 2 + 0];
    float r3v[5];
    r3v[0] = cube_relu(x, hk.x);
    r3v[1] = cube_relu(x, hk.y);
    r3v[2] = cube_relu(x, hk.z);
    r3v[3] = cube_relu(x, hk.w);
    r3v[4] = 0.0f;

    float acc = 0.0f;

    // Iterations in [n, npad) contribute exact +/-0 (all window knots >= x),
    // so padding to a multiple of 4 is bit-neutral and kills the remainder loop.
    const int npad = (n + 3) & ~3;

#pragma unroll 4
    for (int i = 0; i < npad; i++) {
        const float4 rb = sr[i * 2 + 1];       // c4, w, k_break, k_new
        const float4 ra = sr[i * 2 + 0];       // c0..c3

        // one NEW relu+cube per spline (knot m = i+4), rest reused bit-exactly
        r3v[(i + 4) % 5] = cube_relu(x, rb.w);

        const float t0 = __fmul_rn(r3v[(i + 0) % 5], ra.x);
        const float t1 = __fmul_rn(r3v[(i + 1) % 5], ra.y);
        const float t2 = __fmul_rn(r3v[(i + 2) % 5], ra.z);
        const float t3 = __fmul_rn(r3v[(i + 3) % 5], ra.w);
        const float t4 = __fmul_rn(r3v[(i + 4) % 5], rb.x);

        // S3: ((t0+t4)+t2)+(t1+t3)
        const float s = __fadd_rn(__fadd_rn(__fadd_rn(t0, t4), t2),
                                  __fadd_rn(t1, t3));

        acc = __fadd_rn(acc, __fmul_rn(s, rb.y));
    }

    out[bo * FEATURES + f] = acc;
}

extern "C" void kernel_launch(void* const* d_in, const int* in_sizes, int n_in,
                              void* d_out, int out_size) {
    const float* x     = (const float*)d_in[0];
    const float* knots = (const float*)d_in[1];
    const float* w     = (const float*)d_in[2];
    float* out         = (float*)d_out;
    (void)in_sizes; (void)n_in; (void)out_size;

    const int prep_blocks = (FEATURES * NROW + 255) / 256;   // 130
    setup_kernel<<<FEATURES + prep_blocks, 256>>>(x, knots, w);

    dim3 grid(BATCH / 256, FEATURES);
    bspline_kernel<<<grid, 256>>>(out);
}

// round 17
// speedup vs baseline: 2.2468x; 2.2468x over previous
#include <cuda_runtime.h>

#define FEATURES 512
#define NB 64
#define NKNOTS 68
#define BATCH 2048
#define NROW 65   // 64 splines + sentinel row

// Per (feature, spline) row, 2 x float4:
//   ra = (c0, c1, c2, c3)
//   rb = (c4, w, k_break = k[i], k_new = k[i+4])
// Sentinel row i=64: ra = (k0,k1,k2,k3) [prologue knots], rb = (0,0,2.0,0).
__device__ float4 g_rows[FEATURES * NROW * 2];
// Per-feature value-sorted batch: x values and original b indices.
__device__ float g_xs[FEATURES * BATCH];
__device__ int   g_pb[FEATURES * BATCH];

// Merged setup kernel: blocks [0,512) do the per-feature bucket sort,
// blocks [512, 512+130) build the coef/knot rows.
__global__ void __launch_bounds__(256)
setup_kernel(const float* __restrict__ X,
             const float* __restrict__ knots,
             const float* __restrict__ weights) {
    const int t = threadIdx.x;

    if (blockIdx.x < FEATURES) {
        // ---- per-feature counting sort by bucket = floor(64x) ----
        // Any batch permutation is bit-neutral (each out depends only on its x).
        __shared__ int hist[64];
        __shared__ int offs[64];
        const int f = blockIdx.x;

        if (t < 64) hist[t] = 0;
        __syncthreads();

        float xv[8];
        int   bk[8];
#pragma unroll
        for (int r = 0; r < 8; r++) {
            int b = r * 256 + t;
            float x = X[b * FEATURES + f];
            int k = (int)(x * 64.0f);
            k = min(max(k, 0), 63);
            xv[r] = x; bk[r] = k;
            atomicAdd(&hist[k], 1);
        }
        __syncthreads();

        if (t == 0) {
            int s = 0;
#pragma unroll
            for (int i = 0; i < 64; i++) { offs[i] = s; s += hist[i]; }
        }
        __syncthreads();

#pragma unroll
        for (int r = 0; r < 8; r++) {
            int pos = atomicAdd(&offs[bk[r]], 1);
            g_xs[f * BATCH + pos] = xv[r];
            g_pb[f * BATCH + pos] = r * 256 + t;
        }
    } else {
        // ---- row prep ----
        int idx = (blockIdx.x - FEATURES) * 256 + t;   // f*NROW + i
        if (idx >= FEATURES * NROW) return;
        int f = idx / NROW, i = idx % NROW;
        const float* kr = knots + f * NKNOTS;
        float4 ra, rb;
        if (i < NB) {
            float kw[5];
#pragma unroll
            for (int j = 0; j < 5; j++) kw[j] = kr[i + j];
            float c[5];
#pragma unroll
            for (int j = 0; j < 5; j++) {
                float p = 1.0f;                       // P1: sequential left fold
#pragma unroll
                for (int jp = 0; jp < 5; jp++) {
                    float d = (jp == j) ? 1.0f : __fsub_rn(kw[jp], kw[j]);
                    p = __fmul_rn(p, d);
                }
                c[j] = __fdiv_rn(1.0f, p);
            }
            ra = make_float4(c[0], c[1], c[2], c[3]);
            rb = make_float4(c[4], weights[f * NB + i], kr[i], kr[i + 4]);
        } else {
            ra = make_float4(kr[0], kr[1], kr[2], kr[3]);
            rb = make_float4(0.0f, 0.0f, 2.0f, 0.0f);
        }
        g_rows[idx * 2 + 0] = ra;
        g_rows[idx * 2 + 1] = rb;
    }
}

// cube with the exact rounding chain of the reference: (r*r)*r
__device__ __forceinline__ float cube_relu(float x, float k) {
    float r = fmaxf(__fsub_rn(x, k), 0.0f);
    return __fmul_rn(__fmul_rn(r, r), r);
}

__global__ void __launch_bounds__(256)
bspline_kernel(float* __restrict__ out) {
    __shared__ __align__(16) float4 sr[NROW * 2];
    __shared__ float skb[NB];

    const int f = blockIdx.y;
    const int t = threadIdx.x;
    if (t < NROW * 2) sr[t] = g_rows[f * NROW * 2 + t];
    __syncthreads();
    if (t < NB) skb[t] = sr[t * 2 + 1].z;   // break knots k[0..63]
    __syncthreads();

    const int slot = blockIdx.x * 256 + t;
    const float x = g_xs[f * BATCH + slot];     // coalesced, value-sorted
    const int   bo = g_pb[f * BATCH + slot];

    // Trip count n = #{ i < 64 : k_i < x } via branchless binary search
    // (same exact float predicate as the old per-iteration break).
    int n = 0;
#pragma unroll
    for (int s = 32; s >= 1; s >>= 1)
        if (skb[n + s - 1] < x) n += s;          // lower_bound over 63 elems
    if (n == 63 && skb[63] < x) n = 64;

    // Prologue: r3 slots for knots k[0..3] (stored in sentinel row's ra).
    const float4 hk = sr[64 * 2 + 0];
    float r3v[5];
    r3v[0] = cube_relu(x, hk.x);
    r3v[1] = cube_relu(x, hk.y);
    r3v[2] = cube_relu(x, hk.z);
    r3v[3] = cube_relu(x, hk.w);
    r3v[4] = 0.0f;

    float acc = 0.0f;

    // Groups of 5 so the rolling-slot indices (j+k)%5 are compile-time.
    // Padded iterations (i in [n, 5*ngrp)) contribute exact +/-0: real rows
    // there have all window knots >= x (cubes 0), and the sentinel row (i=64,
    // reachable only when n=64) has weight 0.
    const int ngrp = (n + 4) / 5;                // <= 13

    for (int g = 0; g < ngrp; g++) {
        const int base = g * 5;
#pragma unroll
        for (int j = 0; j < 5; j++) {
            const int i = base + j;
            const float4 rb = sr[i * 2 + 1];     // c4, w, k_break, k_new
            const float4 ra = sr[i * 2 + 0];     // c0..c3

            r3v[(j + 4) % 5] = cube_relu(x, rb.w);

            const float t0 = __fmul_rn(r3v[(j + 0) % 5], ra.x);
            const float t1 = __fmul_rn(r3v[(j + 1) % 5], ra.y);
            const float t2 = __fmul_rn(r3v[(j + 2) % 5], ra.z);
            const float t3 = __fmul_rn(r3v[(j + 3) % 5], ra.w);
            const float t4 = __fmul_rn(r3v[(j + 4) % 5], rb.x);

            // S3: ((t0+t4)+t2)+(t1+t3)
            const float s = __fadd_rn(__fadd_rn(__fadd_rn(t0, t4), t2),
                                      __fadd_rn(t1, t3));

            acc = __fadd_rn(acc, __fmul_rn(s, rb.y));
        }
    }

    out[bo * FEATURES + f] = acc;
}

extern "C" void kernel_launch(void* const* d_in, const int* in_sizes, int n_in,
                              void* d_out, int out_size) {
    const float* x     = (const float*)d_in[0];
    const float* knots = (const float*)d_in[1];
    const float* w     = (const float*)d_in[2];
    float* out         = (float*)d_out;
    (void)in_sizes; (void)n_in; (void)out_size;

    const int prep_blocks = (FEATURES * NROW + 255) / 256;   // 130
    setup_kernel<<<FEATURES + prep_blocks, 256>>>(x, knots, w);

    dim3 grid(BATCH / 256, FEATURES);
    bspline_kernel<<<grid, 256>>>(out);
}